// round 4
// baseline (speedup 1.0000x reference)
#include <cuda_runtime.h>
#include <math.h>

#define UNITS 512
#define VOCAB 32000
#define BATCH 128
#define SEQ   64

// Scratch (no cudaMalloc allowed) — referenced directly from device code so
// kernel_launch contains ONLY kernel launches (maximally capture-safe).
__device__ float g_xc[BATCH * 2 * UNITS];   // [x | context]
__device__ float g_G [BATCH * 3 * UNITS];   // xc @ gru_k + gru_b[0]
__device__ float g_y [BATCH * UNITS];       // relu(state @ dW + db)

// ----------------------------------------------------------------------------
// Fused attention: per batch b, compute score = tanh(A @ W0 + b0 + b1) @ vW,
// softmax over seq, context = sum_s alpha[s] * A[s,:]. One block per batch.
// A = attention_inputs[b] is 64x512; tiled 64x64x16 GEMM, 4x4 micro-tiles.
// Writes context into g_xc[b, 512:1024].
// ----------------------------------------------------------------------------
__global__ __launch_bounds__(256) void attn_kernel(
    const float* __restrict__ ai, const float* __restrict__ W0,
    const float* __restrict__ b0v, const float* __restrict__ b1v,
    const float* __restrict__ vW,
    float* __restrict__ alpha_out)
{
    __shared__ float As[16][65];
    __shared__ float Bs[16][68];
    __shared__ float scoreS[SEQ];
    __shared__ float alphaS[SEQ];

    const int b   = blockIdx.x;
    const float* A = ai + (size_t)b * SEQ * UNITS;
    const int tid = threadIdx.x;
    const int tx  = tid & 15;
    const int ty  = tid >> 4;

    const int lr = tid >> 2;          // A-tile: row within 64
    const int lq = tid & 3;           // A-tile: which float4 of the 16-wide K slab
    const int lk = tid >> 4;          // B-tile: k row
    const int lj = (tid & 15) * 4;    // B-tile: col float4

    float rowScore[4] = {0.f, 0.f, 0.f, 0.f};

    for (int jt = 0; jt < UNITS / 64; jt++) {
        const int col0 = jt * 64;
        float acc[4][4] = {};
        for (int k0 = 0; k0 < UNITS; k0 += 16) {
            float4 av = *(const float4*)(A + (size_t)lr * UNITS + k0 + lq * 4);
            As[lq*4+0][lr] = av.x; As[lq*4+1][lr] = av.y;
            As[lq*4+2][lr] = av.z; As[lq*4+3][lr] = av.w;
            float4 bv = *(const float4*)(W0 + (size_t)(k0 + lk) * UNITS + col0 + lj);
            *(float4*)&Bs[lk][lj] = bv;
            __syncthreads();
            #pragma unroll
            for (int k = 0; k < 16; k++) {
                float a0 = As[k][ty*4+0], a1 = As[k][ty*4+1];
                float a2 = As[k][ty*4+2], a3 = As[k][ty*4+3];
                float w0 = Bs[k][tx*4+0], w1 = Bs[k][tx*4+1];
                float w2 = Bs[k][tx*4+2], w3 = Bs[k][tx*4+3];
                acc[0][0] += a0*w0; acc[0][1] += a0*w1; acc[0][2] += a0*w2; acc[0][3] += a0*w3;
                acc[1][0] += a1*w0; acc[1][1] += a1*w1; acc[1][2] += a1*w2; acc[1][3] += a1*w3;
                acc[2][0] += a2*w0; acc[2][1] += a2*w1; acc[2][2] += a2*w2; acc[2][3] += a2*w3;
                acc[3][0] += a3*w0; acc[3][1] += a3*w1; acc[3][2] += a3*w2; acc[3][3] += a3*w3;
            }
            __syncthreads();
        }
        // epilogue: tanh(+bias) * vW, reduce over this thread's 4 cols
        #pragma unroll
        for (int j = 0; j < 4; j++) {
            const int c = col0 + tx * 4 + j;
            const float bb = b0v[c] + b1v[c];
            const float vw = vW[c];
            #pragma unroll
            for (int i = 0; i < 4; i++)
                rowScore[i] += tanhf(acc[i][j] + bb) * vw;
        }
    }

    // reduce rowScore across the 16 tx-threads sharing a row (16-lane segments)
    #pragma unroll
    for (int i = 0; i < 4; i++) {
        float v = rowScore[i];
        #pragma unroll
        for (int off = 8; off >= 1; off >>= 1)
            v += __shfl_down_sync(0xffffffffu, v, off, 16);
        if (tx == 0) scoreS[ty * 4 + i] = v;
    }
    __syncthreads();

    // softmax over 64 scores (warp 0, 2 elements per lane)
    if (tid < 32) {
        float s0 = scoreS[tid], s1 = scoreS[tid + 32];
        float m = fmaxf(s0, s1);
        #pragma unroll
        for (int off = 16; off; off >>= 1)
            m = fmaxf(m, __shfl_xor_sync(0xffffffffu, m, off));
        float e0 = expf(s0 - m), e1 = expf(s1 - m);
        float sum = e0 + e1;
        #pragma unroll
        for (int off = 16; off; off >>= 1)
            sum += __shfl_xor_sync(0xffffffffu, sum, off);
        float inv = 1.f / sum;
        alphaS[tid]      = e0 * inv;
        alphaS[tid + 32] = e1 * inv;
        alpha_out[b * SEQ + tid]      = e0 * inv;
        alpha_out[b * SEQ + tid + 32] = e1 * inv;
    }
    __syncthreads();

    // context[u] = sum_s alpha[s] * A[s][u]  (coalesced over u, A is L1-hot)
    for (int u = tid; u < UNITS; u += 256) {
        float accu = 0.f;
        #pragma unroll 16
        for (int s = 0; s < SEQ; s++)
            accu += alphaS[s] * A[(size_t)s * UNITS + u];
        g_xc[(size_t)b * 2 * UNITS + UNITS + u] = accu;
    }
}

// ----------------------------------------------------------------------------
// Generic tiled GEMM: C = act(A[M,K] @ B[K,N] + bias[N]); ACT 0=none, 1=relu.
// Requires M%64==0, N%64==0, K%16==0 (all shapes here satisfy this).
// ----------------------------------------------------------------------------
template <int ACT>
__global__ __launch_bounds__(256) void gemm_kernel(
    const float* __restrict__ A, const float* __restrict__ B,
    const float* __restrict__ bias, float* __restrict__ C,
    int M, int N, int K)
{
    __shared__ float As[16][65];
    __shared__ float Bs[16][68];

    const int tid = threadIdx.x;
    const int tx  = tid & 15;
    const int ty  = tid >> 4;
    const int row0 = blockIdx.x * 64;
    const int col0 = blockIdx.y * 64;

    const int lr = tid >> 2;
    const int lq = tid & 3;
    const int lk = tid >> 4;
    const int lj = (tid & 15) * 4;

    float acc[4][4] = {};

    for (int k0 = 0; k0 < K; k0 += 16) {
        float4 av = *(const float4*)(A + (size_t)(row0 + lr) * K + k0 + lq * 4);
        As[lq*4+0][lr] = av.x; As[lq*4+1][lr] = av.y;
        As[lq*4+2][lr] = av.z; As[lq*4+3][lr] = av.w;
        float4 bv = *(const float4*)(B + (size_t)(k0 + lk) * N + col0 + lj);
        *(float4*)&Bs[lk][lj] = bv;
        __syncthreads();
        #pragma unroll
        for (int k = 0; k < 16; k++) {
            float a0 = As[k][ty*4+0], a1 = As[k][ty*4+1];
            float a2 = As[k][ty*4+2], a3 = As[k][ty*4+3];
            float w0 = Bs[k][tx*4+0], w1 = Bs[k][tx*4+1];
            float w2 = Bs[k][tx*4+2], w3 = Bs[k][tx*4+3];
            acc[0][0] += a0*w0; acc[0][1] += a0*w1; acc[0][2] += a0*w2; acc[0][3] += a0*w3;
            acc[1][0] += a1*w0; acc[1][1] += a1*w1; acc[1][2] += a1*w2; acc[1][3] += a1*w3;
            acc[2][0] += a2*w0; acc[2][1] += a2*w1; acc[2][2] += a2*w2; acc[2][3] += a2*w3;
            acc[3][0] += a3*w0; acc[3][1] += a3*w1; acc[3][2] += a3*w2; acc[3][3] += a3*w3;
        }
        __syncthreads();
    }

    const int c0 = col0 + tx * 4;
    const float4 bq = *(const float4*)(bias + c0);
    const float bb[4] = {bq.x, bq.y, bq.z, bq.w};
    #pragma unroll
    for (int i = 0; i < 4; i++) {
        float4 v;
        v.x = acc[i][0] + bb[0];
        v.y = acc[i][1] + bb[1];
        v.z = acc[i][2] + bb[2];
        v.w = acc[i][3] + bb[3];
        if (ACT == 1) {
            v.x = fmaxf(v.x, 0.f); v.y = fmaxf(v.y, 0.f);
            v.z = fmaxf(v.z, 0.f); v.w = fmaxf(v.w, 0.f);
        }
        *(float4*)(C + (size_t)(row0 + ty * 4 + i) * N + c0) = v;
    }
}

// ----------------------------------------------------------------------------
// Embedding gather: g_xc[b, 0:512] = emb[inputs[b]]
// ----------------------------------------------------------------------------
__global__ void gather_kernel(const int* __restrict__ idx,
                              const float* __restrict__ emb)
{
    const int b = blockIdx.x;
    const int t = threadIdx.x;  // 128 threads, float4 each = 512 floats
    const float4* src = (const float4*)(emb + (size_t)idx[b] * UNITS);
    float4* dst = (float4*)(g_xc + (size_t)b * 2 * UNITS);
    dst[t] = src[t];
}

// ----------------------------------------------------------------------------
// GRU gemm input wrapper: G = xc @ gru_k + gru_b[0] done by gemm_kernel on g_xc.
// GRU elementwise (h = 0): state = (1 - z) * hh
//   z  = sigmoid(xz + gru_b1[j]);  r = sigmoid(xr + gru_b1[512+j])
//   hh = tanh(xh + r * gru_b1[1024+j])
// ----------------------------------------------------------------------------
__global__ void gru_ew_kernel(const float* __restrict__ gru_b,
                              float* __restrict__ state)
{
    const int i = blockIdx.x * blockDim.x + threadIdx.x;  // 128*512
    const int b = i >> 9;
    const int j = i & 511;
    const float* b1v = gru_b + 3 * UNITS;   // gru_b[1]
    const float xz = g_G[(size_t)b * 3 * UNITS + j];
    const float xr = g_G[(size_t)b * 3 * UNITS + UNITS + j];
    const float xh = g_G[(size_t)b * 3 * UNITS + 2 * UNITS + j];
    const float z  = 1.f / (1.f + expf(-(xz + b1v[j])));
    const float r  = 1.f / (1.f + expf(-(xr + b1v[UNITS + j])));
    const float hh = tanhf(xh + r * b1v[2 * UNITS + j]);
    state[i] = (1.f - z) * hh;
}

// Device-side pointer bridges for the GEMM kernels (so kernel_launch never
// needs cudaGetSymbolAddress). Tiny wrapper kernels pass the global arrays.
__global__ __launch_bounds__(256) void gemm_xc_gruk(
    const float* __restrict__ B, const float* __restrict__ bias)
{
    // forwards to nothing — placeholder removed; see wrappers below
}

// Wrappers that bind scratch globals to the generic GEMM.
template <int ACT>
__global__ __launch_bounds__(256) void gemm_from_xc(
    const float* __restrict__ B, const float* __restrict__ bias,
    float* __restrict__ C, int N, int K)
{
    // Inline the generic gemm with A = g_xc
    __shared__ float As[16][65];
    __shared__ float Bs[16][68];
    const float* A = g_xc;
    const int tid = threadIdx.x;
    const int tx  = tid & 15;
    const int ty  = tid >> 4;
    const int row0 = blockIdx.x * 64;
    const int col0 = blockIdx.y * 64;
    const int lr = tid >> 2;
    const int lq = tid & 3;
    const int lk = tid >> 4;
    const int lj = (tid & 15) * 4;
    float acc[4][4] = {};
    for (int k0 = 0; k0 < K; k0 += 16) {
        float4 av = *(const float4*)(A + (size_t)(row0 + lr) * K + k0 + lq * 4);
        As[lq*4+0][lr] = av.x; As[lq*4+1][lr] = av.y;
        As[lq*4+2][lr] = av.z; As[lq*4+3][lr] = av.w;
        float4 bv = *(const float4*)(B + (size_t)(k0 + lk) * N + col0 + lj);
        *(float4*)&Bs[lk][lj] = bv;
        __syncthreads();
        #pragma unroll
        for (int k = 0; k < 16; k++) {
            float a0 = As[k][ty*4+0], a1 = As[k][ty*4+1];
            float a2 = As[k][ty*4+2], a3 = As[k][ty*4+3];
            float w0 = Bs[k][tx*4+0], w1 = Bs[k][tx*4+1];
            float w2 = Bs[k][tx*4+2], w3 = Bs[k][tx*4+3];
            acc[0][0] += a0*w0; acc[0][1] += a0*w1; acc[0][2] += a0*w2; acc[0][3] += a0*w3;
            acc[1][0] += a1*w0; acc[1][1] += a1*w1; acc[1][2] += a1*w2; acc[1][3] += a1*w3;
            acc[2][0] += a2*w0; acc[2][1] += a2*w1; acc[2][2] += a2*w2; acc[2][3] += a2*w3;
            acc[3][0] += a3*w0; acc[3][1] += a3*w1; acc[3][2] += a3*w2; acc[3][3] += a3*w3;
        }
        __syncthreads();
    }
    const int c0 = col0 + tx * 4;
    const float4 bq = *(const float4*)(bias + c0);
    const float bb[4] = {bq.x, bq.y, bq.z, bq.w};
    #pragma unroll
    for (int i = 0; i < 4; i++) {
        float4 v;
        v.x = acc[i][0] + bb[0];
        v.y = acc[i][1] + bb[1];
        v.z = acc[i][2] + bb[2];
        v.w = acc[i][3] + bb[3];
        if (ACT == 1) {
            v.x = fmaxf(v.x, 0.f); v.y = fmaxf(v.y, 0.f);
            v.z = fmaxf(v.z, 0.f); v.w = fmaxf(v.w, 0.f);
        }
        float* Cdst = (C == nullptr) ? g_G : C;
        *(float4*)(Cdst + (size_t)(row0 + ty * 4 + i) * N + c0) = v;
    }
}

// state @ dW -> g_y (relu), then g_y @ oW -> logits. A comes from param;
// C for the first goes to g_y global.
__global__ __launch_bounds__(256) void gemm_to_y(
    const float* __restrict__ A, const float* __restrict__ B,
    const float* __restrict__ bias, int N, int K)
{
    __shared__ float As[16][65];
    __shared__ float Bs[16][68];
    const int tid = threadIdx.x;
    const int tx  = tid & 15;
    const int ty  = tid >> 4;
    const int row0 = blockIdx.x * 64;
    const int col0 = blockIdx.y * 64;
    const int lr = tid >> 2;
    const int lq = tid & 3;
    const int lk = tid >> 4;
    const int lj = (tid & 15) * 4;
    float acc[4][4] = {};
    for (int k0 = 0; k0 < K; k0 += 16) {
        float4 av = *(const float4*)(A + (size_t)(row0 + lr) * K + k0 + lq * 4);
        As[lq*4+0][lr] = av.x; As[lq*4+1][lr] = av.y;
        As[lq*4+2][lr] = av.z; As[lq*4+3][lr] = av.w;
        float4 bv = *(const float4*)(B + (size_t)(k0 + lk) * N + col0 + lj);
        *(float4*)&Bs[lk][lj] = bv;
        __syncthreads();
        #pragma unroll
        for (int k = 0; k < 16; k++) {
            float a0 = As[k][ty*4+0], a1 = As[k][ty*4+1];
            float a2 = As[k][ty*4+2], a3 = As[k][ty*4+3];
            float w0 = Bs[k][tx*4+0], w1 = Bs[k][tx*4+1];
            float w2 = Bs[k][tx*4+2], w3 = Bs[k][tx*4+3];
            acc[0][0] += a0*w0; acc[0][1] += a0*w1; acc[0][2] += a0*w2; acc[0][3] += a0*w3;
            acc[1][0] += a1*w0; acc[1][1] += a1*w1; acc[1][2] += a1*w2; acc[1][3] += a1*w3;
            acc[2][0] += a2*w0; acc[2][1] += a2*w1; acc[2][2] += a2*w2; acc[2][3] += a2*w3;
            acc[3][0] += a3*w0; acc[3][1] += a3*w1; acc[3][2] += a3*w2; acc[3][3] += a3*w3;
        }
        __syncthreads();
    }
    const int c0 = col0 + tx * 4;
    const float4 bq = *(const float4*)(bias + c0);
    const float bb[4] = {bq.x, bq.y, bq.z, bq.w};
    #pragma unroll
    for (int i = 0; i < 4; i++) {
        float4 v;
        v.x = fmaxf(acc[i][0] + bb[0], 0.f);
        v.y = fmaxf(acc[i][1] + bb[1], 0.f);
        v.z = fmaxf(acc[i][2] + bb[2], 0.f);
        v.w = fmaxf(acc[i][3] + bb[3], 0.f);
        *(float4*)(g_y + (size_t)(row0 + ty * 4 + i) * N + c0) = v;
    }
}

__global__ __launch_bounds__(256) void gemm_from_y(
    const float* __restrict__ B, const float* __restrict__ bias,
    float* __restrict__ C, int N, int K)
{
    __shared__ float As[16][65];
    __shared__ float Bs[16][68];
    const float* A = g_y;
    const int tid = threadIdx.x;
    const int tx  = tid & 15;
    const int ty  = tid >> 4;
    const int row0 = blockIdx.x * 64;
    const int col0 = blockIdx.y * 64;
    const int lr = tid >> 2;
    const int lq = tid & 3;
    const int lk = tid >> 4;
    const int lj = (tid & 15) * 4;
    float acc[4][4] = {};
    for (int k0 = 0; k0 < K; k0 += 16) {
        float4 av = *(const float4*)(A + (size_t)(row0 + lr) * K + k0 + lq * 4);
        As[lq*4+0][lr] = av.x; As[lq*4+1][lr] = av.y;
        As[lq*4+2][lr] = av.z; As[lq*4+3][lr] = av.w;
        float4 bv = *(const float4*)(B + (size_t)(k0 + lk) * N + col0 + lj);
        *(float4*)&Bs[lk][lj] = bv;
        __syncthreads();
        #pragma unroll
        for (int k = 0; k < 16; k++) {
            float a0 = As[k][ty*4+0], a1 = As[k][ty*4+1];
            float a2 = As[k][ty*4+2], a3 = As[k][ty*4+3];
            float w0 = Bs[k][tx*4+0], w1 = Bs[k][tx*4+1];
            float w2 = Bs[k][tx*4+2], w3 = Bs[k][tx*4+3];
            acc[0][0] += a0*w0; acc[0][1] += a0*w1; acc[0][2] += a0*w2; acc[0][3] += a0*w3;
            acc[1][0] += a1*w0; acc[1][1] += a1*w1; acc[1][2] += a1*w2; acc[1][3] += a1*w3;
            acc[2][0] += a2*w0; acc[2][1] += a2*w1; acc[2][2] += a2*w2; acc[2][3] += a2*w3;
            acc[3][0] += a3*w0; acc[3][1] += a3*w1; acc[3][2] += a3*w2; acc[3][3] += a3*w3;
        }
        __syncthreads();
    }
    const int c0 = col0 + tx * 4;
    const float4 bq = *(const float4*)(bias + c0);
    const float bb[4] = {bq.x, bq.y, bq.z, bq.w};
    #pragma unroll
    for (int i = 0; i < 4; i++) {
        float4 v;
        v.x = acc[i][0] + bb[0];
        v.y = acc[i][1] + bb[1];
        v.z = acc[i][2] + bb[2];
        v.w = acc[i][3] + bb[3];
        *(float4*)(C + (size_t)(row0 + ty * 4 + i) * N + c0) = v;
    }
}

// ----------------------------------------------------------------------------
extern "C" void kernel_launch(void* const* d_in, const int* in_sizes, int n_in,
                              void* d_out, int out_size)
{
    const int*   inputs = (const int*)  d_in[0];
    const float* ai     = (const float*)d_in[1];
    const float* W0     = (const float*)d_in[2];
    const float* b0v    = (const float*)d_in[3];
    // d_in[4] = W1 (dead: hidden0 == 0)
    const float* b1v    = (const float*)d_in[5];
    const float* vW     = (const float*)d_in[6];
    // d_in[7] = vb (softmax-invariant constant; alpha unaffected)
    const float* emb    = (const float*)d_in[8];
    const float* gru_k  = (const float*)d_in[9];
    // d_in[10] = gru_rk (dead: h == 0)
    const float* gru_b  = (const float*)d_in[11];
    const float* dW     = (const float*)d_in[12];
    const float* dbv    = (const float*)d_in[13];
    const float* oW     = (const float*)d_in[14];
    const float* obv    = (const float*)d_in[15];

    float* out    = (float*)d_out;
    float* logits = out;                                   // [128, 32000]
    float* state  = out + (size_t)BATCH * VOCAB;           // [128, 512]
    float* alpha  = state + (size_t)BATCH * UNITS;         // [128, 64]

    // independent producers (write into g_xc)
    gather_kernel<<<BATCH, 128>>>(inputs, emb);
    attn_kernel<<<BATCH, 256>>>(ai, W0, b0v, b1v, vW, alpha);

    // G = xc @ gru_k + gru_b[0]          (128 x 1536, K = 1024) -> g_G
    gemm_from_xc<0><<<dim3(2, 24), 256>>>(gru_k, gru_b, nullptr,
                                          3 * UNITS, 2 * UNITS);
    // state = (1 - z) * hh
    gru_ew_kernel<<<BATCH, UNITS>>>(gru_b, state);

    // y = relu(state @ dW + db)          (128 x 512, K = 512) -> g_y
    gemm_to_y<<<dim3(2, 8), 256>>>(state, dW, dbv, UNITS, UNITS);
    // logits = y @ oW + ob               (128 x 32000, K = 512)
    gemm_from_y<<<dim3(2, 500), 256>>>(oW, obv, logits, VOCAB, UNITS);
}

// round 6
// speedup vs baseline: 1.3384x; 1.3384x over previous
#include <cuda_runtime.h>
#include <math.h>

#define UNITS 512
#define VOCAB 32000
#define BATCH 128
#define SEQ   64

typedef unsigned long long ull;

// Scratch (no cudaMalloc allowed) — referenced directly from device code.
__device__ float g_xc[BATCH * 2 * UNITS];     // [x | context]
__device__ float g_G [BATCH * 3 * UNITS];     // xc @ gru_k + gru_b[0]
__device__ float g_y [BATCH * UNITS];         // relu(state @ dW + db)
__device__ float g_spart[8][BATCH * SEQ];     // per-col-tile partial scores

// ---- packed f32x2 helpers (exact fp32 FMA on both lanes) --------------------
__device__ __forceinline__ ull pack2(float v) {
    ull r; asm("mov.b64 %0, {%1,%1};" : "=l"(r) : "f"(v)); return r;
}
__device__ __forceinline__ void fma2(ull &d, ull a, ull b) {
    asm("fma.rn.f32x2 %0, %1, %2, %0;" : "+l"(d) : "l"(a), "l"(b));
}
__device__ __forceinline__ float2 unpack2(ull v) {
    float lo, hi; asm("mov.b64 {%0,%1}, %2;" : "=f"(lo), "=f"(hi) : "l"(v));
    return make_float2(lo, hi);
}

// ----------------------------------------------------------------------------
// escore: partial attention scores. Treat attention_inputs as A[8192,512].
// Block (bx,by) computes 64x64 tile of e = tanh(A@W0 + b0 + b1), dots with vW,
// reduces over the 64 cols, writes partial score to g_spart[by][row].
// grid(128, 8), 256 threads, f32x2 inner loop.
// ----------------------------------------------------------------------------
__global__ __launch_bounds__(256) void escore_kernel(
    const float* __restrict__ A, const float* __restrict__ W0,
    const float* __restrict__ b0v, const float* __restrict__ b1v,
    const float* __restrict__ vW)
{
    __shared__ ull   As2[16][65];   // duplicated pairs {v,v}
    __shared__ float Bs [16][72];

    const int tid = threadIdx.x;
    const int tx  = tid & 15;
    const int ty  = tid >> 4;
    const int row0 = blockIdx.x * 64;
    const int col0 = blockIdx.y * 64;
    const int lr = tid >> 2, lq = tid & 3;
    const int lk = tid >> 4, lj = (tid & 15) * 4;

    ull acc[4][2] = {};

    for (int k0 = 0; k0 < UNITS; k0 += 16) {
        float4 av = *(const float4*)(A + (size_t)(row0 + lr) * UNITS + k0 + lq * 4);
        As2[lq*4+0][lr] = pack2(av.x);
        As2[lq*4+1][lr] = pack2(av.y);
        As2[lq*4+2][lr] = pack2(av.z);
        As2[lq*4+3][lr] = pack2(av.w);
        *(float4*)&Bs[lk][lj] =
            *(const float4*)(W0 + (size_t)(k0 + lk) * UNITS + col0 + lj);
        __syncthreads();
        #pragma unroll
        for (int k = 0; k < 16; k++) {
            ull w0 = *(const ull*)&Bs[k][tx*4];
            ull w1 = *(const ull*)&Bs[k][tx*4+2];
            #pragma unroll
            for (int i = 0; i < 4; i++) {
                ull a = As2[k][ty*4+i];
                fma2(acc[i][0], a, w0);
                fma2(acc[i][1], a, w1);
            }
        }
        __syncthreads();
    }

    const int c0 = col0 + tx * 4;
    const float bb0 = b0v[c0]   + b1v[c0];
    const float bb1 = b0v[c0+1] + b1v[c0+1];
    const float bb2 = b0v[c0+2] + b1v[c0+2];
    const float bb3 = b0v[c0+3] + b1v[c0+3];
    const float v0 = vW[c0], v1 = vW[c0+1], v2 = vW[c0+2], v3 = vW[c0+3];

    #pragma unroll
    for (int i = 0; i < 4; i++) {
        float2 p0 = unpack2(acc[i][0]);
        float2 p1 = unpack2(acc[i][1]);
        float s = tanhf(p0.x + bb0) * v0 + tanhf(p0.y + bb1) * v1
                + tanhf(p1.x + bb2) * v2 + tanhf(p1.y + bb3) * v3;
        #pragma unroll
        for (int off = 8; off >= 1; off >>= 1)
            s += __shfl_down_sync(0xffffffffu, s, off, 16);
        if (tx == 0) g_spart[blockIdx.y][row0 + ty*4 + i] = s;
    }
}

// ----------------------------------------------------------------------------
// softmax + context per batch: sum the 8 partials, softmax over 64, write
// alpha, then context[u] = sum_s alpha[s]*A[s][u] into g_xc upper half.
// ----------------------------------------------------------------------------
__global__ __launch_bounds__(256) void softmax_ctx_kernel(
    const float* __restrict__ ai, float* __restrict__ alpha_out)
{
    __shared__ float alphaS[SEQ];
    const int b = blockIdx.x;
    const int tid = threadIdx.x;
    const float* A = ai + (size_t)b * SEQ * UNITS;

    if (tid < 32) {
        float s0 = 0.f, s1 = 0.f;
        #pragma unroll
        for (int j = 0; j < 8; j++) {
            s0 += g_spart[j][b * SEQ + tid];
            s1 += g_spart[j][b * SEQ + tid + 32];
        }
        float m = fmaxf(s0, s1);
        #pragma unroll
        for (int off = 16; off; off >>= 1)
            m = fmaxf(m, __shfl_xor_sync(0xffffffffu, m, off));
        float e0 = expf(s0 - m), e1 = expf(s1 - m);
        float sum = e0 + e1;
        #pragma unroll
        for (int off = 16; off; off >>= 1)
            sum += __shfl_xor_sync(0xffffffffu, sum, off);
        float inv = 1.f / sum;
        alphaS[tid]      = e0 * inv;
        alphaS[tid + 32] = e1 * inv;
        alpha_out[b * SEQ + tid]      = e0 * inv;
        alpha_out[b * SEQ + tid + 32] = e1 * inv;
    }
    __syncthreads();

    for (int u = tid; u < UNITS; u += 256) {
        float acc = 0.f;
        #pragma unroll 16
        for (int s = 0; s < SEQ; s++)
            acc += alphaS[s] * A[(size_t)s * UNITS + u];
        g_xc[(size_t)b * 2 * UNITS + UNITS + u] = acc;
    }
}

// ----------------------------------------------------------------------------
// gemm64: 64x64 tile, f32x2. ASRC: 0=param, 1=g_xc. CDST: 0=param, 1=g_G,
// 2=g_y. ACT: 0=none, 1=relu. Requires M%64==0, N%64==0, K%16==0.
// ----------------------------------------------------------------------------
template <int ASRC, int CDST, int ACT>
__global__ __launch_bounds__(256) void gemm64(
    const float* __restrict__ Ap, const float* __restrict__ B,
    const float* __restrict__ bias, float* __restrict__ Cp,
    int N, int K)
{
    __shared__ ull   As2[16][65];
    __shared__ float Bs [16][72];

    const float* A = (ASRC == 1) ? g_xc : Ap;
    float*       C = (CDST == 1) ? g_G : (CDST == 2) ? g_y : Cp;

    const int tid = threadIdx.x;
    const int tx  = tid & 15;
    const int ty  = tid >> 4;
    const int row0 = blockIdx.x * 64;
    const int col0 = blockIdx.y * 64;
    const int lr = tid >> 2, lq = tid & 3;
    const int lk = tid >> 4, lj = (tid & 15) * 4;

    ull acc[4][2] = {};

    for (int k0 = 0; k0 < K; k0 += 16) {
        float4 av = *(const float4*)(A + (size_t)(row0 + lr) * K + k0 + lq * 4);
        As2[lq*4+0][lr] = pack2(av.x);
        As2[lq*4+1][lr] = pack2(av.y);
        As2[lq*4+2][lr] = pack2(av.z);
        As2[lq*4+3][lr] = pack2(av.w);
        *(float4*)&Bs[lk][lj] =
            *(const float4*)(B + (size_t)(k0 + lk) * N + col0 + lj);
        __syncthreads();
        #pragma unroll
        for (int k = 0; k < 16; k++) {
            ull w0 = *(const ull*)&Bs[k][tx*4];
            ull w1 = *(const ull*)&Bs[k][tx*4+2];
            #pragma unroll
            for (int i = 0; i < 4; i++) {
                ull a = As2[k][ty*4+i];
                fma2(acc[i][0], a, w0);
                fma2(acc[i][1], a, w1);
            }
        }
        __syncthreads();
    }

    const int c0 = col0 + tx * 4;
    const float4 bq = *(const float4*)(bias + c0);
    #pragma unroll
    for (int i = 0; i < 4; i++) {
        float2 p0 = unpack2(acc[i][0]);
        float2 p1 = unpack2(acc[i][1]);
        float4 v;
        v.x = p0.x + bq.x; v.y = p0.y + bq.y;
        v.z = p1.x + bq.z; v.w = p1.y + bq.w;
        if (ACT == 1) {
            v.x = fmaxf(v.x, 0.f); v.y = fmaxf(v.y, 0.f);
            v.z = fmaxf(v.z, 0.f); v.w = fmaxf(v.w, 0.f);
        }
        *(float4*)(C + (size_t)(row0 + ty * 4 + i) * N + c0) = v;
    }
}

// ----------------------------------------------------------------------------
// gemm128: 128x64 tile (8x4 microtile), A = g_y [128,512] fixed, C = logits.
// grid(1, N/64). Each oW column tile is read exactly once.
// ----------------------------------------------------------------------------
__global__ __launch_bounds__(256) void gemm128_logits(
    const float* __restrict__ B, const float* __restrict__ bias,
    float* __restrict__ C)
{
    __shared__ ull   As2[16][129];
    __shared__ float Bs [16][72];

    const int tid = threadIdx.x;
    const int tx  = tid & 15;
    const int ty  = tid >> 4;                  // 0..15, rows ty*8+i
    const int col0 = blockIdx.y * 64;
    const int lr  = tid >> 1;                  // 0..127
    const int lqq = (tid & 1) * 8;             // k-offset 0 or 8
    const int lk = tid >> 4, lj = (tid & 15) * 4;

    ull acc[8][2] = {};

    for (int k0 = 0; k0 < UNITS; k0 += 16) {
        float4 a0 = *(const float4*)(g_y + (size_t)lr * UNITS + k0 + lqq);
        float4 a1 = *(const float4*)(g_y + (size_t)lr * UNITS + k0 + lqq + 4);
        As2[lqq+0][lr] = pack2(a0.x);
        As2[lqq+1][lr] = pack2(a0.y);
        As2[lqq+2][lr] = pack2(a0.z);
        As2[lqq+3][lr] = pack2(a0.w);
        As2[lqq+4][lr] = pack2(a1.x);
        As2[lqq+5][lr] = pack2(a1.y);
        As2[lqq+6][lr] = pack2(a1.z);
        As2[lqq+7][lr] = pack2(a1.w);
        *(float4*)&Bs[lk][lj] =
            *(const float4*)(B + (size_t)(k0 + lk) * VOCAB + col0 + lj);
        __syncthreads();
        #pragma unroll
        for (int k = 0; k < 16; k++) {
            ull w0 = *(const ull*)&Bs[k][tx*4];
            ull w1 = *(const ull*)&Bs[k][tx*4+2];
            #pragma unroll
            for (int i = 0; i < 8; i++) {
                ull a = As2[k][ty*8+i];
                fma2(acc[i][0], a, w0);
                fma2(acc[i][1], a, w1);
            }
        }
        __syncthreads();
    }

    const int c0 = col0 + tx * 4;
    const float4 bq = *(const float4*)(bias + c0);
    #pragma unroll
    for (int i = 0; i < 8; i++) {
        float2 p0 = unpack2(acc[i][0]);
        float2 p1 = unpack2(acc[i][1]);
        float4 v;
        v.x = p0.x + bq.x; v.y = p0.y + bq.y;
        v.z = p1.x + bq.z; v.w = p1.y + bq.w;
        *(float4*)(C + (size_t)(ty * 8 + i) * VOCAB + c0) = v;
    }
}

// ----------------------------------------------------------------------------
// Embedding gather: g_xc[b, 0:512] = emb[inputs[b]]
// ----------------------------------------------------------------------------
__global__ void gather_kernel(const int* __restrict__ idx,
                              const float* __restrict__ emb)
{
    const int b = blockIdx.x;
    const int t = threadIdx.x;  // 128 threads x float4 = 512 floats
    const float4* src = (const float4*)(emb + (size_t)idx[b] * UNITS);
    float4* dst = (float4*)(g_xc + (size_t)b * 2 * UNITS);
    dst[t] = src[t];
}

// ----------------------------------------------------------------------------
// GRU elementwise (h = 0): state = (1 - z) * hh
// ----------------------------------------------------------------------------
__global__ void gru_ew_kernel(const float* __restrict__ gru_b,
                              float* __restrict__ state)
{
    const int i = blockIdx.x * blockDim.x + threadIdx.x;  // 128*512
    const int b = i >> 9;
    const int j = i & 511;
    const float* b1v = gru_b + 3 * UNITS;   // gru_b[1]
    const float xz = g_G[(size_t)b * 3 * UNITS + j];
    const float xr = g_G[(size_t)b * 3 * UNITS + UNITS + j];
    const float xh = g_G[(size_t)b * 3 * UNITS + 2 * UNITS + j];
    const float z  = 1.f / (1.f + expf(-(xz + b1v[j])));
    const float r  = 1.f / (1.f + expf(-(xr + b1v[UNITS + j])));
    const float hh = tanhf(xh + r * b1v[2 * UNITS + j]);
    state[i] = (1.f - z) * hh;
}

// ----------------------------------------------------------------------------
extern "C" void kernel_launch(void* const* d_in, const int* in_sizes, int n_in,
                              void* d_out, int out_size)
{
    const int*   inputs = (const int*)  d_in[0];
    const float* ai     = (const float*)d_in[1];
    const float* W0     = (const float*)d_in[2];
    const float* b0v    = (const float*)d_in[3];
    // d_in[4] = W1 (dead: hidden0 == 0)
    const float* b1v    = (const float*)d_in[5];
    const float* vW     = (const float*)d_in[6];
    // d_in[7] = vb (softmax-invariant; alpha unaffected)
    const float* emb    = (const float*)d_in[8];
    const float* gru_k  = (const float*)d_in[9];
    // d_in[10] = gru_rk (dead: h == 0)
    const float* gru_b  = (const float*)d_in[11];
    const float* dW     = (const float*)d_in[12];
    const float* dbv    = (const float*)d_in[13];
    const float* oW     = (const float*)d_in[14];
    const float* obv    = (const float*)d_in[15];

    float* out    = (float*)d_out;
    float* logits = out;                                   // [128, 32000]
    float* state  = out + (size_t)BATCH * VOCAB;           // [128, 512]
    float* alpha  = state + (size_t)BATCH * UNITS;         // [128, 64]

    // independent producers
    gather_kernel<<<BATCH, 128>>>(inputs, emb);
    escore_kernel<<<dim3(128, 8), 256>>>(ai, W0, b0v, b1v, vW);
    softmax_ctx_kernel<<<BATCH, 256>>>(ai, alpha);

    // G = xc @ gru_k + gru_b[0]          (128 x 1536, K = 1024) -> g_G
    gemm64<1, 1, 0><<<dim3(2, 24), 256>>>(nullptr, gru_k, gru_b, nullptr,
                                          3 * UNITS, 2 * UNITS);
    // state = (1 - z) * hh
    gru_ew_kernel<<<BATCH, UNITS>>>(gru_b, state);

    // y = relu(state @ dW + db)          (128 x 512) -> g_y
    gemm64<0, 2, 1><<<dim3(2, 8), 256>>>(state, dW, dbv, nullptr,
                                         UNITS, UNITS);
    // logits = y @ oW + ob               (128 x 32000, K = 512)
    gemm128_logits<<<dim3(1, 500), 256>>>(oW, obv, logits);
}